// round 5
// baseline (speedup 1.0000x reference)
#include <cuda_runtime.h>

#define DEGREE   6
#define WIDTH    7          // DEGREE - START_DEGREE + 1
#define FEAT     1024       // in_features
#define OUTF     1024       // out_features
#define THREADS  512
#define NWARPS   16
#define ROWS_PER_BLOCK 4    // 4 warps per row, 8 features per lane

// Low-register, high-occupancy fused kernel:
//  - 4 warps cooperate on one batch row (256 feats each, 2x LDG.128/lane)
//  - warp-shuffle reduce -> s_part[16][7]; threads 0..27 merge quarters ->
//    s_basis[4][7]; coeff loads (14 floats/thread) issued between barriers
//  - phase 2: each thread emits 4 rows x 2 output columns (float2 stores)
__global__ __launch_bounds__(THREADS, 3)
void hermite_fused_kernel(const float* __restrict__ x,
                          const float* __restrict__ coeffs,
                          const float* __restrict__ sigma,
                          float* __restrict__ out)
{
    __shared__ float s_part[NWARPS][WIDTH];
    __shared__ float s_basis[ROWS_PER_BLOCK][WIDTH];

    const int tid  = threadIdx.x;
    const int lane = tid & 31;
    const int warp = tid >> 5;          // 0..15
    const int rloc = warp >> 2;         // row within block, 0..3
    const int quad = warp & 3;          // which 256-feature quarter

    const float s     = fminf(fmaxf(sigma[0], 0.1f), 5.0f);
    const float inv_s = 1.0f / s;

    // ---- Phase 1: quarter-row per warp (8 features/lane, front-batched) ----
    const int row = blockIdx.x * ROWS_PER_BLOCK + rloc;
    const float4* xr = reinterpret_cast<const float4*>(x + (size_t)row * FEAT)
                       + quad * 64;     // 64 float4 per quarter

    float4 xv0 = xr[lane];
    float4 xv1 = xr[lane + 32];

    float acc[WIDTH];
#pragma unroll
    for (int w = 0; w < WIDTH; ++w) acc[w] = 0.0f;

    const float xe[8] = { xv0.x, xv0.y, xv0.z, xv0.w,
                          xv1.x, xv1.y, xv1.z, xv1.w };

#pragma unroll
    for (int e = 0; e < 8; ++e) {
        const float xs = xe[e] * inv_s;
        // min(xs*xs, 50) never binds for these inputs; even if it did, the
        // difference (~e-50) is far below the 1e-3 tolerance.
        const float g  = __expf(-(xs * xs));

        float hm2 = 1.0f;          // H0
        float hm1 = 2.0f * xs;     // H1 (unclipped, as in reference)
        acc[0] += g;               // g * H0
        acc[1] += g * hm1;

        const float two_xs = 2.0f * xs;
#pragma unroll
        for (int n = 2; n <= DEGREE; ++n) {
            float h = two_xs * hm1 - (2.0f * (float)(n - 1)) * hm2;
            h = fminf(fmaxf(h, -100.0f), 100.0f);  // clip BEFORE recursion use
            acc[n] += g * h;
            hm2 = hm1;
            hm1 = h;
        }
    }

    // ---- warp-local reduction of the 7 accumulators ----
#pragma unroll
    for (int w = 0; w < WIDTH; ++w) {
#pragma unroll
        for (int off = 16; off > 0; off >>= 1)
            acc[w] += __shfl_xor_sync(0xffffffffu, acc[w], off);
    }
    if (lane == 0) {
#pragma unroll
        for (int w = 0; w < WIDTH; ++w)
            s_part[warp][w] = acc[w];
    }

    __syncthreads();

    // ---- coeff loads for phase 2 (lifetime starts only here) ----
    // thread tid owns output columns {2*tid, 2*tid+1}: 14 contiguous floats,
    // 8-byte aligned -> 7x LDG.64. Latency hidden behind merge + barrier.
    float cf[14];
    {
        const float2* c2 =
            reinterpret_cast<const float2*>(coeffs + (size_t)(tid * 2) * WIDTH);
#pragma unroll
        for (int i = 0; i < 7; ++i) {
            float2 v = c2[i];
            cf[2 * i]     = v.x;
            cf[2 * i + 1] = v.y;
        }
    }

    // ---- merge the 4 quarter-row partials (threads 0..27) ----
    if (tid < ROWS_PER_BLOCK * WIDTH) {
        const int rr = tid / WIDTH;
        const int w  = tid % WIDTH;
        s_basis[rr][w] = (s_part[rr * 4 + 0][w] + s_part[rr * 4 + 1][w])
                       + (s_part[rr * 4 + 2][w] + s_part[rr * 4 + 3][w]);
    }

    __syncthreads();

    // ---- Phase 2: 4 rows x 2 output columns per thread ----
#pragma unroll
    for (int r = 0; r < ROWS_PER_BLOCK; ++r) {
        float bs[WIDTH];
#pragma unroll
        for (int w = 0; w < WIDTH; ++w)
            bs[w] = s_basis[r][w];     // broadcast LDS, conflict-free

        float2 o;
        float v0 = 0.0f, v1 = 0.0f;
#pragma unroll
        for (int w = 0; w < WIDTH; ++w) {
            v0 += bs[w] * cf[w];           // column 2*tid
            v1 += bs[w] * cf[WIDTH + w];   // column 2*tid + 1
        }
        o.x = v0;
        o.y = v1;

        const int orow = blockIdx.x * ROWS_PER_BLOCK + r;
        reinterpret_cast<float2*>(out + (size_t)orow * OUTF)[tid] = o;
    }
}

extern "C" void kernel_launch(void* const* d_in, const int* in_sizes, int n_in,
                              void* d_out, int out_size)
{
    const float* x      = (const float*)d_in[0];   // (4096, 1024)
    const float* coeffs = (const float*)d_in[1];   // (1024, 7)
    const float* sigma  = (const float*)d_in[2];   // (1,)
    float* out          = (float*)d_out;           // (4096, 1024)

    const int batch  = in_sizes[0] / FEAT;         // 4096
    const int nblock = batch / ROWS_PER_BLOCK;     // 1024

    hermite_fused_kernel<<<nblock, THREADS>>>(x, coeffs, sigma, out);
}

// round 6
// speedup vs baseline: 1.1278x; 1.1278x over previous
#include <cuda_runtime.h>

#define DEGREE   6
#define WIDTH    7          // DEGREE - START_DEGREE + 1
#define FEAT     1024       // in_features
#define OUTF     1024       // out_features
#define THREADS  256
#define NWARPS   8
#define ROWS_PER_BLOCK 4    // 2 warps per row, 16 features per lane

typedef unsigned long long u64;
union uf2 { u64 u; float2 f; };

// ---- packed f32x2 helpers (sm_100+/sm_103a, PTX-only instructions) ----
__device__ __forceinline__ u64 pack2(float lo, float hi) {
    u64 r; asm("mov.b64 %0, {%1, %2};" : "=l"(r) : "f"(lo), "f"(hi)); return r;
}
__device__ __forceinline__ u64 mul2(u64 a, u64 b) {
    u64 r; asm("mul.rn.f32x2 %0, %1, %2;" : "=l"(r) : "l"(a), "l"(b)); return r;
}
__device__ __forceinline__ u64 add2(u64 a, u64 b) {
    u64 r; asm("add.rn.f32x2 %0, %1, %2;" : "=l"(r) : "l"(a), "l"(b)); return r;
}
__device__ __forceinline__ u64 fma2(u64 a, u64 b, u64 c) {
    u64 r; asm("fma.rn.f32x2 %0, %1, %2, %3;" : "=l"(r) : "l"(a), "l"(b), "l"(c)); return r;
}
__device__ __forceinline__ float ex2f(float x) {
    float r; asm("ex2.approx.f32 %0, %1;" : "=f"(r) : "f"(x)); return r;
}
// clip both halves to [-100, 100] (scalar FMNMX on the pair halves: alu pipe)
__device__ __forceinline__ u64 clip2(u64 v) {
    uf2 t; t.u = v;
    t.f.x = fminf(fmaxf(t.f.x, -100.0f), 100.0f);
    t.f.y = fminf(fmaxf(t.f.y, -100.0f), 100.0f);
    return t.u;
}

// R4 structure + packed-f32x2 Hermite evaluation.
__global__ __launch_bounds__(THREADS)
void hermite_fused_kernel(const float* __restrict__ x,
                          const float* __restrict__ coeffs,
                          const float* __restrict__ sigma,
                          float* __restrict__ out)
{
    __shared__ float s_part[NWARPS][WIDTH];

    const int tid  = threadIdx.x;
    const int lane = tid & 31;
    const int warp = tid >> 5;

    const float s     = fminf(fmaxf(sigma[0], 0.1f), 5.0f);
    const float inv_s = 1.0f / s;

    // packed per-thread constants (hoisted by compiler)
    const u64 inv_s2 = pack2(inv_s, inv_s);
    const u64 nl2e2  = pack2(-1.4426950408889634f, -1.4426950408889634f);
    u64 cn2[5];   // -(2(n-1)) for n = 2..6
#pragma unroll
    for (int n = 2; n <= DEGREE; ++n)
        cn2[n - 2] = pack2(-2.0f * (float)(n - 1), -2.0f * (float)(n - 1));

    // ---- Phase 1: half a row per warp (16 features/lane, front-batched) ----
    const int row  = blockIdx.x * ROWS_PER_BLOCK + (warp >> 1);
    const int half = warp & 1;
    const float4* xr = reinterpret_cast<const float4*>(x + (size_t)row * FEAT)
                       + half * (FEAT / 8);   // 128 float4 per half

    float4 xv[4];
#pragma unroll
    for (int i = 0; i < 4; ++i) xv[i] = xr[lane + 32 * i];

    u64 acc[WIDTH];
#pragma unroll
    for (int w = 0; w < WIDTH; ++w) acc[w] = 0ull;   // +0.0f, +0.0f

#pragma unroll
    for (int i = 0; i < 4; ++i) {
        u64 xp[2] = { pack2(xv[i].x, xv[i].y), pack2(xv[i].z, xv[i].w) };
#pragma unroll
        for (int p = 0; p < 2; ++p) {
            const u64 xs  = mul2(xp[p], inv_s2);
            const u64 xs2 = mul2(xs, xs);
            // min(xs^2,50) dropped: never binds here; delta ~e-50 << 1e-3 tol
            uf2 ea; ea.u  = mul2(xs2, nl2e2);        // -log2(e) * xs^2
            const u64 g   = pack2(ex2f(ea.f.x), ex2f(ea.f.y));
            const u64 txs = add2(xs, xs);            // 2*xs = H1 (unclipped)

            acc[0] = add2(acc[0], g);                // g * H0
            acc[1] = fma2(g, txs, acc[1]);           // g * H1

            u64 hm2 = pack2(1.0f, 1.0f);
            u64 hm1 = txs;
#pragma unroll
            for (int n = 2; n <= DEGREE; ++n) {
                const u64 t = mul2(cn2[n - 2], hm2); // -(2(n-1))*hm2
                u64 h = fma2(txs, hm1, t);           // 2xs*hm1 - 2(n-1)*hm2
                h = clip2(h);                        // clip BEFORE recursion use
                acc[n] = fma2(g, h, acc[n]);
                hm2 = hm1;
                hm1 = h;
            }
        }
    }

    // collapse packed halves -> scalar accumulators
    float a[WIDTH];
#pragma unroll
    for (int w = 0; w < WIDTH; ++w) {
        uf2 t; t.u = acc[w];
        a[w] = t.f.x + t.f.y;
    }

    // ---- coeff loads (phase 2), issued here so latency hides behind
    //      the shuffle reduction + barrier ----
    float4 c[7];
    {
        const float4* c4 =
            reinterpret_cast<const float4*>(coeffs + (size_t)(tid * 4) * WIDTH);
#pragma unroll
        for (int i = 0; i < 7; ++i) c[i] = c4[i];
    }

    // ---- warp-local reduction of the 7 accumulators ----
#pragma unroll
    for (int w = 0; w < WIDTH; ++w) {
#pragma unroll
        for (int off = 16; off > 0; off >>= 1)
            a[w] += __shfl_xor_sync(0xffffffffu, a[w], off);
    }
    if (lane == 0) {
#pragma unroll
        for (int w = 0; w < WIDTH; ++w)
            s_part[warp][w] = a[w];
    }

    __syncthreads();   // the ONLY barrier

    // ---- Phase 2: 4 rows x 4 outputs per thread from register coeffs ----
    const float* cf = reinterpret_cast<const float*>(c);

#pragma unroll
    for (int r = 0; r < ROWS_PER_BLOCK; ++r) {
        float bs[WIDTH];
#pragma unroll
        for (int w = 0; w < WIDTH; ++w)
            bs[w] = s_part[2 * r][w] + s_part[2 * r + 1][w];  // merge halves

        float4 o;
        float* op = reinterpret_cast<float*>(&o);
#pragma unroll
        for (int i = 0; i < 4; ++i) {
            float v = 0.0f;
#pragma unroll
            for (int w = 0; w < WIDTH; ++w)
                v += bs[w] * cf[i * WIDTH + w];
            op[i] = v;
        }
        const int orow = blockIdx.x * ROWS_PER_BLOCK + r;
        reinterpret_cast<float4*>(out + (size_t)orow * OUTF)[tid] = o;
    }
}

extern "C" void kernel_launch(void* const* d_in, const int* in_sizes, int n_in,
                              void* d_out, int out_size)
{
    const float* x      = (const float*)d_in[0];   // (4096, 1024)
    const float* coeffs = (const float*)d_in[1];   // (1024, 7)
    const float* sigma  = (const float*)d_in[2];   // (1,)
    float* out          = (float*)d_out;           // (4096, 1024)

    const int batch  = in_sizes[0] / FEAT;         // 4096
    const int nblock = batch / ROWS_PER_BLOCK;     // 1024

    hermite_fused_kernel<<<nblock, THREADS>>>(x, coeffs, sigma, out);
}